// round 4
// baseline (speedup 1.0000x reference)
#include <cuda_runtime.h>
#include <stdint.h>

// filtfilt(butter(4)) over 512 rows x 32768 fp32 samples.
// R4: 2 segments/row (split at S=16399, chosen ==3 mod 4 so every memory
// phase is 16B-aligned), 66KB smem -> 3 blocks/SM. IIR runs on 64 threads
// with 260-sample chunks (+80 warm-up from zero state; max pole 0.795 ->
// residual ~1e-8); all IIR loops use LDS.128/STS.128 (lane stride 260 floats
// == 16B mod 128B -> conflict-free). Fill and output are aligned float4
// copies. Normalization by max|x| skipped (linear pipeline; rounding only).

#define T_LEN  32768
#define PAD    15
#define TE     (T_LEN + 2 * PAD)   /* 32798 */
#define SSPL   16399               /* segment split, ==3 mod 4 */
#define NTH    128
#define NIIR   64
#define C      260                 /* chunk len, mult of 4 */
#define W      80                  /* warm-up samples */
#define SMLEN  16480

#define B0f  0.0048243445989025905f
#define B1f  0.019297378395610362f
#define B2f  0.028946067593415543f
#define NA1f 2.369513007182038f      /* -a1 */
#define NA2f (-2.3139884144002064f)  /* -a2 */
#define NA3f 1.0546654058785661f     /* -a3 */
#define NA4f (-0.18737949236818502f) /* -a4 */

struct St { float z1, z2, z3, z4; };

__device__ __forceinline__ float stepf(float xv, St& s) {
    float y  = fmaf(B0f, xv, s.z1);
    float t1 = fmaf(B1f, xv, s.z2);
    float t2 = fmaf(B2f, xv, s.z3);
    float t3 = fmaf(B1f, xv, s.z4);   // b3 == b1
    float t4 = B0f * xv;              // b4 == b0
    s.z1 = fmaf(NA1f, y, t1);
    s.z2 = fmaf(NA2f, y, t2);
    s.z3 = fmaf(NA3f, y, t3);
    s.z4 = fmaf(NA4f, y, t4);
    return y;
}

// ascending read-only [lo, hi)
__device__ __forceinline__ void fwd_ro(const float* q, int lo, int hi, St& st) {
    while (lo < hi && (((uintptr_t)(q + lo)) & 15)) stepf(q[lo++], st);
    #pragma unroll 2
    for (; lo + 4 <= hi; lo += 4) {
        float4 v = *(const float4*)(q + lo);
        stepf(v.x, st); stepf(v.y, st); stepf(v.z, st); stepf(v.w, st);
    }
    for (; lo < hi; ++lo) stepf(q[lo], st);
}
// ascending read-write [lo, hi)
__device__ __forceinline__ void fwd_rw(float* q, int lo, int hi, St& st) {
    while (lo < hi && (((uintptr_t)(q + lo)) & 15)) { q[lo] = stepf(q[lo], st); ++lo; }
    #pragma unroll 2
    for (; lo + 4 <= hi; lo += 4) {
        float4 v = *(float4*)(q + lo);
        v.x = stepf(v.x, st); v.y = stepf(v.y, st);
        v.z = stepf(v.z, st); v.w = stepf(v.w, st);
        *(float4*)(q + lo) = v;
    }
    for (; lo < hi; ++lo) q[lo] = stepf(q[lo], st);
}
// descending read-only, p = hi down to lo inclusive
__device__ __forceinline__ void bwd_ro(const float* q, int hi, int lo, St& st) {
    int p = hi;
    while (p >= lo && (((uintptr_t)(q + p + 1)) & 15)) stepf(q[p--], st);
    #pragma unroll 2
    for (; p - 3 >= lo; p -= 4) {
        float4 v = *(const float4*)(q + p - 3);
        stepf(v.w, st); stepf(v.z, st); stepf(v.y, st); stepf(v.x, st);
    }
    for (; p >= lo; --p) stepf(q[p], st);
}
// descending read-write
__device__ __forceinline__ void bwd_rw(float* q, int hi, int lo, St& st) {
    int p = hi;
    while (p >= lo && (((uintptr_t)(q + p + 1)) & 15)) { q[p] = stepf(q[p], st); --p; }
    #pragma unroll 2
    for (; p - 3 >= lo; p -= 4) {
        float4 v = *(float4*)(q + p - 3);
        v.w = stepf(v.w, st); v.z = stepf(v.z, st);
        v.y = stepf(v.y, st); v.x = stepf(v.x, st);
        *(float4*)(q + p - 3) = v;
    }
    for (; p >= lo; --p) q[p] = stepf(q[p], st);
}

__global__ void __launch_bounds__(NTH)
filtfilt_r4_kernel(const float* __restrict__ x, float* __restrict__ out) {
    extern __shared__ float sm[];
    const int tid = threadIdx.x;
    const int row = blockIdx.x >> 1;
    const int seg = blockIdx.x & 1;
    const float* __restrict__ xr = x + (size_t)row * T_LEN;

    // seg0: e in [0, 16479), q = sm+1  (x[j] at sm[j+16], aligned)
    // seg1: e in [16319, 32798), q = sm-16319 (x[j] at sm[j-16304], aligned)
    const int E0 = seg ? (SSPL - W) : 0;
    const int E1 = seg ? TE : (SSPL + W);
    float* __restrict__ q = seg ? (sm - 16319) : (sm + 1);

    // ---- fill: aligned float4 copy + reflection samples ----
    {
        const float4* __restrict__ xv =
            (const float4*)(xr + (seg ? 16304 : 0));
        float4* __restrict__ sv = (float4*)(sm + (seg ? 0 : 16));
        #pragma unroll 4
        for (int i = tid; i < 4116; i += NTH) sv[i] = xv[i];
    }
    if (tid < PAD) {
        if (seg == 0) {
            q[tid] = 2.0f * xr[0] - xr[PAD - tid];
        } else {
            const int e = TE - PAD + tid;
            q[e] = 2.0f * xr[T_LEN - 1] - xr[65549 - e];
        }
    }
    __syncthreads();

    // ---------------- forward pass over [seg_lo, E1) ----------------
    {
        St st = {0.f, 0.f, 0.f, 0.f};
        const bool act = (tid < NIIR);
        int c_lo = 0, c_hi = 0;
        if (act) {
            if (seg == 0) {
                c_lo = tid ? (3 + tid * C) : 0;   // thread 0 absorbs 3-sample head
                c_hi = min(3 + (tid + 1) * C, E1);
            } else {
                c_lo = SSPL + tid * C;
                c_hi = min(c_lo + C, TE);
            }
            const int w_lo = max(E0, c_lo - W);
            fwd_ro(q, w_lo, c_lo, st);
        }
        __syncthreads();                         // warm reads before chunk writes
        if (act) fwd_rw(q, c_lo, c_hi, st);
    }
    __syncthreads();

    // ---------------- backward pass over [seg_lo, seg_hi) -----------
    {
        St st = {0.f, 0.f, 0.f, 0.f};
        const bool act = (tid < NIIR);
        int bc_hi = 0, bc_lo = 0;
        if (act) {
            const int lo_lim = seg ? SSPL : 0;
            bc_hi = (seg ? (TE - 1) : (SSPL - 1)) - tid * C;
            bc_lo = max(lo_lim, bc_hi - C + 1);
            const int w_hi = min(E1 - 1, bc_hi + W);
            bwd_ro(q, w_hi, bc_hi + 1, st);
        }
        __syncthreads();
        if (act) bwd_rw(q, bc_hi, bc_lo, st);
    }
    __syncthreads();

    // ---- output: aligned float4 copy of this segment's center samples ----
    {
        const int t0 = seg ? 16384 : 0;          // out index base, %4==0
        const float4* __restrict__ s4 = (const float4*)(q + t0 + PAD);
        float4* __restrict__ o4 = (float4*)(out + (size_t)row * T_LEN + t0);
        #pragma unroll 4
        for (int i = tid; i < 4096; i += NTH) o4[i] = s4[i];
    }
}

extern "C" void kernel_launch(void* const* d_in, const int* in_sizes, int n_in,
                              void* d_out, int out_size) {
    const float* x = (const float*)d_in[0];
    float* out = (float*)d_out;
    const int rows = out_size / T_LEN;   // 512
    cudaFuncSetAttribute(filtfilt_r4_kernel,
                         cudaFuncAttributeMaxDynamicSharedMemorySize,
                         SMLEN * sizeof(float));
    filtfilt_r4_kernel<<<rows * 2, NTH, SMLEN * sizeof(float)>>>(x, out);
}

// round 6
// speedup vs baseline: 1.6287x; 1.6287x over previous
#include <cuda_runtime.h>

// filtfilt(butter(4)) over 512 rows x 32768 fp32 samples.
// R5 = R3 geometry (2 segments/row, 128 IIR threads, 66KB smem, 3 blocks/SM)
// with vectorized IIR smem access (LDS.128/STS.128) and W=80->64.
// Chunk grids are constructed so float4 groups are 16B-aligned after <=3
// scalar head steps; all smem indexing is integer offsets into sm[] (no
// pointer selects) so ptxas keeps the shared address space.
// Split S=16399; seg0: xe(e)=sm[e+1], seg1: xe(e)=sm[e-16335].
// Chunk C=132 (132 floats = 528B == 16B mod 128B -> conflict-free lanes).
// Warm-up W=64 from zero state (max pole 0.795 -> residual ~4e-7).
// max|x| normalization skipped (linear pipeline, rounding-level change).

#define T_LEN  32768
#define PAD    15
#define TE     (T_LEN + 2 * PAD)   /* 32798 */
#define S      16399               /* split, ==3 mod 4 -> out halves %4==0 */
#define NTH    128
#define C      132
#define W      64
#define SMLEN  16480

#define B0f  0.0048243445989025905f
#define B1f  0.019297378395610362f
#define B2f  0.028946067593415543f
#define NA1f 2.369513007182038f      /* -a1 */
#define NA2f (-2.3139884144002064f)  /* -a2 */
#define NA3f 1.0546654058785661f     /* -a3 */
#define NA4f (-0.18737949236818502f) /* -a4 */

struct St { float z1, z2, z3, z4; };

__device__ __forceinline__ float stepf(float xv, St& s) {
    float y  = fmaf(B0f, xv, s.z1);
    float t1 = fmaf(B1f, xv, s.z2);
    float t2 = fmaf(B2f, xv, s.z3);
    float t3 = fmaf(B1f, xv, s.z4);   // b3 == b1
    float t4 = B0f * xv;              // b4 == b0
    s.z1 = fmaf(NA1f, y, t1);
    s.z2 = fmaf(NA2f, y, t2);
    s.z3 = fmaf(NA3f, y, t3);
    s.z4 = fmaf(NA4f, y, t4);
    return y;
}

// ascending over smem indices [i, end)
__device__ __forceinline__ void fwd_ro(const float* s, int i, int end, St& st) {
    for (; i < end && (i & 3); ++i) stepf(s[i], st);
    #pragma unroll 2
    for (; i + 4 <= end; i += 4) {
        float4 v = *(const float4*)(s + i);
        stepf(v.x, st); stepf(v.y, st); stepf(v.z, st); stepf(v.w, st);
    }
    for (; i < end; ++i) stepf(s[i], st);
}
__device__ __forceinline__ void fwd_rw(float* s, int i, int end, St& st) {
    for (; i < end && (i & 3); ++i) s[i] = stepf(s[i], st);
    #pragma unroll 2
    for (; i + 4 <= end; i += 4) {
        float4 v = *(float4*)(s + i);
        v.x = stepf(v.x, st); v.y = stepf(v.y, st);
        v.z = stepf(v.z, st); v.w = stepf(v.w, st);
        *(float4*)(s + i) = v;
    }
    for (; i < end; ++i) s[i] = stepf(s[i], st);
}
// descending over smem indices i down to lo (inclusive)
__device__ __forceinline__ void bwd_ro(const float* s, int i, int lo, St& st) {
    for (; i >= lo && ((i & 3) != 3); --i) stepf(s[i], st);
    #pragma unroll 2
    for (; i - 3 >= lo; i -= 4) {
        float4 v = *(const float4*)(s + i - 3);
        stepf(v.w, st); stepf(v.z, st); stepf(v.y, st); stepf(v.x, st);
    }
    for (; i >= lo; --i) stepf(s[i], st);
}
__device__ __forceinline__ void bwd_rw(float* s, int i, int lo, St& st) {
    for (; i >= lo && ((i & 3) != 3); --i) { s[i] = stepf(s[i], st); }
    #pragma unroll 2
    for (; i - 3 >= lo; i -= 4) {
        float4 v = *(float4*)(s + i - 3);
        v.w = stepf(v.w, st); v.z = stepf(v.z, st);
        v.y = stepf(v.y, st); v.x = stepf(v.x, st);
        *(float4*)(s + i - 3) = v;
    }
    for (; i >= lo; --i) s[i] = stepf(s[i], st);
}

__global__ void __launch_bounds__(NTH)
filtfilt_r5_kernel(const float* __restrict__ x, float* __restrict__ out) {
    extern __shared__ float sm[];
    const int tid = threadIdx.x;
    const int row = blockIdx.x >> 1;
    const int seg = blockIdx.x & 1;
    const float* __restrict__ xr = x + (size_t)row * T_LEN;

    // qoff: xe(e) = sm[e + qoff]
    const int qoff = seg ? -16335 : 1;
    const int E0   = seg ? (S - W) : 0;        // 16335 / 0
    const int E1   = seg ? TE : (S + W);       // 32798 / 16463

    // ---- fill: aligned float4 copy of x range ----
    {
        // seg0: x[0..16452) at sm[16+j];  seg1: x[16320..32768) at sm[j-16320]
        const float4* __restrict__ xv = (const float4*)(xr + (seg ? 16320 : 0));
        float4* __restrict__ sv = (float4*)(sm + (seg ? 0 : 16));
        const int n4 = seg ? 4112 : 4113;
        #pragma unroll 4
        for (int i = tid; i < n4; i += NTH) sv[i] = xv[i];
    }
    // ---- reflection samples ----
    if (tid < PAD) {
        if (seg == 0) {
            sm[tid + 1] = 2.0f * xr[0] - xr[PAD - tid];          // e = tid
        } else {
            const int e = TE - PAD + tid;                        // [32783, 32798)
            sm[e - 16335] = 2.0f * xr[T_LEN - 1] - xr[65549 - e];
        }
    }
    __syncthreads();

    // ---------------- forward pass over [seg_lo, E1) ----------------
    {
        St st = {0.f, 0.f, 0.f, 0.f};
        int c_lo, c_hi;
        if (seg == 0) {
            c_lo = tid ? (3 + tid * C) : 0;     // thread 0 absorbs [0,3)
            c_hi = min(3 + (tid + 1) * C, E1);
        } else {
            c_lo = S + tid * C;
            c_hi = min(c_lo + C, TE);
        }
        const bool act = c_lo < E1;
        if (act) fwd_ro(sm, max(E0, c_lo - W) + qoff, c_lo + qoff, st);
        __syncthreads();                        // warm reads before chunk writes
        if (act) fwd_rw(sm, c_lo + qoff, c_hi + qoff, st);
    }
    __syncthreads();

    // ---------------- backward pass over [seg_lo, seg_hi) -----------
    {
        St st = {0.f, 0.f, 0.f, 0.f};
        const int lo_lim = seg ? S : 0;
        const int bc_hi = (seg ? (TE - 1) : (S - 1)) - tid * C;  // inclusive
        const int bc_lo = max(lo_lim, bc_hi - C + 1);
        const bool act = bc_hi >= lo_lim;
        if (act) {
            const int w_hi = min(E1 - 1, bc_hi + W);
            bwd_ro(sm, w_hi + qoff, bc_hi + 1 + qoff, st);
        }
        __syncthreads();
        if (act) bwd_rw(sm, bc_hi + qoff, bc_lo + qoff, st);
    }
    __syncthreads();

    // ---- output: aligned float4 copy (4096 groups per segment) ----
    {
        const int t0 = seg ? 16384 : 0;         // out base, %4==0
        // smidx of (t0 + PAD): seg0 -> 16, seg1 -> 64; both %4==0
        const float4* __restrict__ s4 = (const float4*)(sm + (t0 + PAD + qoff));
        float4* __restrict__ o4 = (float4*)(out + (size_t)row * T_LEN + t0);
        #pragma unroll 4
        for (int i = tid; i < 4096; i += NTH) o4[i] = s4[i];
    }
}

extern "C" void kernel_launch(void* const* d_in, const int* in_sizes, int n_in,
                              void* d_out, int out_size) {
    const float* x = (const float*)d_in[0];
    float* out = (float*)d_out;
    const int rows = out_size / T_LEN;   // 512
    cudaFuncSetAttribute(filtfilt_r5_kernel,
                         cudaFuncAttributeMaxDynamicSharedMemorySize,
                         SMLEN * sizeof(float));
    filtfilt_r5_kernel<<<rows * 2, NTH, SMLEN * sizeof(float)>>>(x, out);
}